// round 1
// baseline (speedup 1.0000x reference)
#include <cuda_runtime.h>
#include <math.h>

#define NB  512
#define NN  32
#define DSA 64
#define DH  128

// Transposed weights scratch: Wt[k][h], h contiguous -> coalesced warp reads.
__device__ float g_Wt_msg1[128 * DH];  // k' < 2*SA = 128
__device__ float g_Wt_msg2[256 * DH];  // k' < 2*H  = 256
__device__ float g_Wt_up1 [192 * DH];  // k' < SA+H = 192
__device__ float g_Wt_up2 [192 * DH];

__global__ void transpose_weights_kernel(const float* __restrict__ Wm1,
                                         const float* __restrict__ Wm2,
                                         const float* __restrict__ Wu1,
                                         const float* __restrict__ Wu2) {
    const int stride = gridDim.x * blockDim.x;
    const int t0 = blockIdx.x * blockDim.x + threadIdx.x;
    for (int i = t0; i < DH * 128; i += stride) {
        int h = i >> 7, k = i & 127;
        g_Wt_msg1[k * DH + h] = Wm1[i];
    }
    for (int i = t0; i < DH * 256; i += stride) {
        int h = i >> 8, k = i & 255;
        g_Wt_msg2[k * DH + h] = Wm2[i];
    }
    for (int i = t0; i < DH * 192; i += stride) {
        int h = i / 192, k = i % 192;
        g_Wt_up1[k * DH + h] = Wu1[i];
        g_Wt_up2[k * DH + h] = Wu2[i];
    }
}

__global__ void __launch_bounds__(128)
msggraph_kernel(const float* __restrict__ x,
                const float* __restrict__ bm1,
                const float* __restrict__ bm2,
                const float* __restrict__ bu1,
                const float* __restrict__ bu2,
                const float* __restrict__ Wv,
                const float* __restrict__ bv,
                float* __restrict__ out)
{
    __shared__ float xs[NN][DSA];   // 8 KB, original x for this batch
    __shared__ float P[NN][DH];     // 16 KB ping buffer: agg1 -> v1 -> agg2
    __shared__ float red[4];

    const int b = blockIdx.x;
    const int h = threadIdx.x;      // output channel 0..127

    // Load x[b] into shared.
    const float* xb = x + b * (NN * DSA);
    #pragma unroll
    for (int i = 0; i < (NN * DSA) / 128; i++) {
        int idx = i * 128 + h;
        ((float*)xs)[idx] = xb[idx];
    }
    __syncthreads();

    float agg[NN];
    float vacc[NN];

    // ================= Layer 1: msg + agg =================
    // e1[p*n+q][h] = relu(A[p] + B[q] + bm1[h]); agg[i] = sum_{j!=i} e1[j*n+i]
    {
        float accA[NN], accB[NN];
        #pragma unroll
        for (int j = 0; j < NN; j++) { accA[j] = 0.f; accB[j] = 0.f; }
        const float* Wl = g_Wt_msg1 + h;             // W_msg1[:, :SA]^T
        const float* Wr = g_Wt_msg1 + DSA * DH + h;  // W_msg1[:, SA:]^T
        for (int k = 0; k < DSA; k++) {
            float wl = Wl[k * DH];
            float wr = Wr[k * DH];
            #pragma unroll
            for (int j = 0; j < NN; j++) {
                float xv = xs[j][k];
                accA[j] = fmaf(xv, wl, accA[j]);
                accB[j] = fmaf(xv, wr, accB[j]);
            }
        }
        float bm = bm1[h];
        #pragma unroll
        for (int j = 0; j < NN; j++) accA[j] += bm;
        #pragma unroll
        for (int i = 0; i < NN; i++) {
            float bi = accB[i];
            float s = -fmaxf(accA[i] + bi, 0.f);   // remove diagonal term
            #pragma unroll
            for (int j = 0; j < NN; j++) s += fmaxf(accA[j] + bi, 0.f);
            agg[i] = s;
        }
    }
    #pragma unroll
    for (int i = 0; i < NN; i++) P[i][h] = agg[i];
    __syncthreads();

    // ================= Layer 1: update =================
    // v1[i][h] = relu( x[i,:]·Wu1[h,:64] + agg[i,:]·Wu1[h,64:] + bu1[h] )
    {
        #pragma unroll
        for (int i = 0; i < NN; i++) vacc[i] = 0.f;
        const float* Wu = g_Wt_up1 + h;
        for (int k = 0; k < DSA; k++) {
            float w = Wu[k * DH];
            #pragma unroll
            for (int i = 0; i < NN; i++) vacc[i] = fmaf(xs[i][k], w, vacc[i]);
        }
        for (int k = 0; k < DH; k++) {
            float w = Wu[(DSA + k) * DH];
            #pragma unroll
            for (int i = 0; i < NN; i++) vacc[i] = fmaf(P[i][k], w, vacc[i]);
        }
        float bu = bu1[h];
        __syncthreads();   // everyone done reading P (agg1)
        #pragma unroll
        for (int i = 0; i < NN; i++) P[i][h] = fmaxf(vacc[i] + bu, 0.f);
    }
    __syncthreads();

    // ================= Layer 2: msg + agg =================
    {
        float accA[NN], accB[NN];
        #pragma unroll
        for (int j = 0; j < NN; j++) { accA[j] = 0.f; accB[j] = 0.f; }
        const float* Wl = g_Wt_msg2 + h;
        const float* Wr = g_Wt_msg2 + DH * DH + h;
        for (int k = 0; k < DH; k++) {
            float wl = Wl[k * DH];
            float wr = Wr[k * DH];
            #pragma unroll
            for (int j = 0; j < NN; j++) {
                float v = P[j][k];
                accA[j] = fmaf(v, wl, accA[j]);
                accB[j] = fmaf(v, wr, accB[j]);
            }
        }
        float bm = bm2[h];
        #pragma unroll
        for (int j = 0; j < NN; j++) accA[j] += bm;
        #pragma unroll
        for (int i = 0; i < NN; i++) {
            float bi = accB[i];
            float s = -fmaxf(accA[i] + bi, 0.f);
            #pragma unroll
            for (int j = 0; j < NN; j++) s += fmaxf(accA[j] + bi, 0.f);
            agg[i] = s;
        }
    }
    __syncthreads();   // everyone done reading P (v1)
    #pragma unroll
    for (int i = 0; i < NN; i++) P[i][h] = agg[i];
    __syncthreads();

    // ================= Layer 2: update + max =================
    float m = -INFINITY;
    {
        #pragma unroll
        for (int i = 0; i < NN; i++) vacc[i] = 0.f;
        const float* Wu = g_Wt_up2 + h;
        for (int k = 0; k < DSA; k++) {
            float w = Wu[k * DH];
            #pragma unroll
            for (int i = 0; i < NN; i++) vacc[i] = fmaf(xs[i][k], w, vacc[i]);
        }
        for (int k = 0; k < DH; k++) {
            float w = Wu[(DSA + k) * DH];
            #pragma unroll
            for (int i = 0; i < NN; i++) vacc[i] = fmaf(P[i][k], w, vacc[i]);
        }
        float bu = bu2[h];
        #pragma unroll
        for (int i = 0; i < NN; i++)
            m = fmaxf(m, fmaxf(vacc[i] + bu, 0.f));
    }

    // out[b] = sum_h m[h] * Wv[h] + bv
    float contrib = m * Wv[h];
    #pragma unroll
    for (int o = 16; o; o >>= 1)
        contrib += __shfl_xor_sync(0xffffffffu, contrib, o);
    if ((h & 31) == 0) red[h >> 5] = contrib;
    __syncthreads();
    if (h == 0) out[b] = red[0] + red[1] + red[2] + red[3] + bv[0];
}

extern "C" void kernel_launch(void* const* d_in, const int* in_sizes, int n_in,
                              void* d_out, int out_size) {
    const float* x   = (const float*)d_in[0];
    // d_in[1] = ext_adj (unused: structure folded into the agg loop)
    const float* Wm1 = (const float*)d_in[2];
    const float* bm1 = (const float*)d_in[3];
    const float* Wm2 = (const float*)d_in[4];
    const float* bm2 = (const float*)d_in[5];
    const float* Wu1 = (const float*)d_in[6];
    const float* bu1 = (const float*)d_in[7];
    const float* Wu2 = (const float*)d_in[8];
    const float* bu2 = (const float*)d_in[9];
    const float* Wv  = (const float*)d_in[10];
    const float* bv  = (const float*)d_in[11];

    transpose_weights_kernel<<<72, 256>>>(Wm1, Wm2, Wu1, Wu2);
    msggraph_kernel<<<NB, 128>>>(x, bm1, bm2, bu1, bu2, Wv, bv, (float*)d_out);
}

// round 2
// speedup vs baseline: 1.5676x; 1.5676x over previous
#include <cuda_runtime.h>
#include <math.h>

#define NB  512
#define NN  32
#define DSA 64
#define DH  128
#define PITCH 34   // floats per shared row: even (8B-aligned pairs), (34%32)=2 -> <=2-way conflicts

typedef unsigned long long u64;

// ---------- f32x2 helpers (Blackwell packed fp32) ----------
__device__ __forceinline__ u64 f2_fma(u64 a, u64 b, u64 c) {
    u64 d; asm("fma.rn.f32x2 %0,%1,%2,%3;" : "=l"(d) : "l"(a), "l"(b), "l"(c)); return d;
}
__device__ __forceinline__ u64 f2_add(u64 a, u64 b) {
    u64 d; asm("add.rn.f32x2 %0,%1,%2;" : "=l"(d) : "l"(a), "l"(b)); return d;
}
__device__ __forceinline__ u64 f2_mul(u64 a, u64 b) {
    u64 d; asm("mul.rn.f32x2 %0,%1,%2;" : "=l"(d) : "l"(a), "l"(b)); return d;
}
__device__ __forceinline__ u64 f2_pack(float lo, float hi) {
    u64 d; asm("mov.b64 %0,{%1,%2};" : "=l"(d) : "f"(lo), "f"(hi)); return d;
}
__device__ __forceinline__ float2 f2_unpack(u64 a) {
    float2 r; asm("mov.b64 {%0,%1},%2;" : "=f"(r.x), "=f"(r.y) : "l"(a)); return r;
}
// 2*relu(t) per lane, exact: t + |t|
__device__ __forceinline__ u64 f2_relu2x(u64 t) {
    return f2_add(t, t & 0x7fffffff7fffffffULL);
}
#define HALF2 0x3F0000003F000000ULL  // {0.5f, 0.5f}

// Transposed weights scratch: Wt[k][h], h contiguous -> coalesced warp reads.
__device__ float g_Wt_msg1[128 * DH];
__device__ float g_Wt_msg2[256 * DH];
__device__ float g_Wt_up1 [192 * DH];
__device__ float g_Wt_up2 [192 * DH];

__global__ void transpose_weights_kernel(const float* __restrict__ Wm1,
                                         const float* __restrict__ Wm2,
                                         const float* __restrict__ Wu1,
                                         const float* __restrict__ Wu2) {
    const int stride = gridDim.x * blockDim.x;
    const int t0 = blockIdx.x * blockDim.x + threadIdx.x;
    for (int i = t0; i < DH * 128; i += stride) {
        int h = i >> 7, k = i & 127;
        g_Wt_msg1[k * DH + h] = Wm1[i];
    }
    for (int i = t0; i < DH * 256; i += stride) {
        int h = i >> 8, k = i & 255;
        g_Wt_msg2[k * DH + h] = Wm2[i];
    }
    for (int i = t0; i < DH * 192; i += stride) {
        int h = i / 192, k = i % 192;
        g_Wt_up1[k * DH + h] = Wu1[i];
        g_Wt_up2[k * DH + h] = Wu2[i];
    }
}

__global__ void __launch_bounds__(128)
msggraph_kernel(const float* __restrict__ x,
                const float* __restrict__ bm1,
                const float* __restrict__ bm2,
                const float* __restrict__ bu1,
                const float* __restrict__ bu2,
                const float* __restrict__ Wv,
                const float* __restrict__ bv,
                float* __restrict__ out)
{
    __shared__ __align__(16) float xsT[DSA * PITCH];  // [k][j], k<64
    __shared__ __align__(16) float PT [DH  * PITCH];  // [k][i], k<128 : agg1 -> v1 -> agg2
    __shared__ float red[4];

    const int b = blockIdx.x;
    const int h = threadIdx.x;      // output channel 0..127

    // Load x[b] (row-major [j=32][k=64]) into transposed shared xsT[k][j].
    const float* xb = x + b * (NN * DSA);
    #pragma unroll
    for (int it = 0; it < (NN * DSA) / 128; it++) {
        int idx = it * 128 + h;
        int j = idx >> 6, k = idx & 63;
        xsT[k * PITCH + j] = xb[idx];
    }
    __syncthreads();

    u64 accA[16], accB[16];   // paired over j: lane0=even j, lane1=odd j
    u64 vacc[16];

    // ================= Layer 1: msg =================
    // A[j] = x[j]·Wl[h], B[j] = x[j]·Wr[h];  e[j*n+i] = relu(A[j]+bm + B[i])
    {
        #pragma unroll
        for (int j2 = 0; j2 < 16; j2++) { accA[j2] = 0; accB[j2] = 0; }
        const float* Wl = g_Wt_msg1 + h;
        const float* Wr = g_Wt_msg1 + DSA * DH + h;
        #pragma unroll 4
        for (int k = 0; k < DSA; k++) {
            float wl = Wl[k * DH], wr = Wr[k * DH];
            u64 wl2 = f2_pack(wl, wl), wr2 = f2_pack(wr, wr);
            const u64* xr = reinterpret_cast<const u64*>(xsT) + k * (PITCH / 2);
            #pragma unroll
            for (int j2 = 0; j2 < 16; j2++) {
                u64 xv = xr[j2];
                accA[j2] = f2_fma(xv, wl2, accA[j2]);
                accB[j2] = f2_fma(xv, wr2, accB[j2]);
            }
        }
        float bm = bm1[h];
        u64 bmp = f2_pack(bm, bm);
        #pragma unroll
        for (int j2 = 0; j2 < 16; j2++) accA[j2] = f2_add(accA[j2], bmp);
        // agg[i] = sum_j relu(A[j]+B[i]) - relu(A[i]+B[i]); write PT[h][i]
        #pragma unroll 4
        for (int i2 = 0; i2 < 16; i2++) {
            float2 bB = f2_unpack(accB[i2]);
            u64 bx = f2_pack(bB.x, bB.x), by = f2_pack(bB.y, bB.y);
            u64 sx = 0, sy = 0;
            #pragma unroll
            for (int j2 = 0; j2 < 16; j2++) {
                u64 A = accA[j2];
                sx = f2_fma(f2_relu2x(f2_add(A, bx)), HALF2, sx);
                sy = f2_fma(f2_relu2x(f2_add(A, by)), HALF2, sy);
            }
            float2 fx = f2_unpack(sx), fy = f2_unpack(sy);
            float2 aA = f2_unpack(accA[i2]);
            float gx = fx.x + fx.y - fmaxf(aA.x + bB.x, 0.f);
            float gy = fy.x + fy.y - fmaxf(aA.y + bB.y, 0.f);
            *reinterpret_cast<u64*>(&PT[h * PITCH + 2 * i2]) = f2_pack(gx, gy);
        }
    }
    __syncthreads();

    // ================= Layer 1: update =================
    // v1[i][h] = relu( x[i]·Wu1[h,:64] + agg[i]·Wu1[h,64:] + bu1[h] )
    {
        #pragma unroll
        for (int i2 = 0; i2 < 16; i2++) vacc[i2] = 0;
        const float* Wu = g_Wt_up1 + h;
        #pragma unroll 4
        for (int k = 0; k < DSA; k++) {
            float w = Wu[k * DH];
            u64 w2 = f2_pack(w, w);
            const u64* xr = reinterpret_cast<const u64*>(xsT) + k * (PITCH / 2);
            #pragma unroll
            for (int i2 = 0; i2 < 16; i2++) vacc[i2] = f2_fma(xr[i2], w2, vacc[i2]);
        }
        #pragma unroll 4
        for (int k = 0; k < DH; k++) {
            float w = Wu[(DSA + k) * DH];
            u64 w2 = f2_pack(w, w);
            const u64* pr = reinterpret_cast<const u64*>(PT) + k * (PITCH / 2);
            #pragma unroll
            for (int i2 = 0; i2 < 16; i2++) vacc[i2] = f2_fma(pr[i2], w2, vacc[i2]);
        }
        float bu = bu1[h];
        u64 bup = f2_pack(bu, bu);
        __syncthreads();   // all warps done reading PT(agg1)
        #pragma unroll
        for (int i2 = 0; i2 < 16; i2++) {
            u64 t = f2_add(vacc[i2], bup);
            *reinterpret_cast<u64*>(&PT[h * PITCH + 2 * i2]) =
                f2_mul(f2_relu2x(t), HALF2);   // relu(t)
        }
    }
    __syncthreads();

    // ================= Layer 2: msg =================
    {
        #pragma unroll
        for (int j2 = 0; j2 < 16; j2++) { accA[j2] = 0; accB[j2] = 0; }
        const float* Wl = g_Wt_msg2 + h;
        const float* Wr = g_Wt_msg2 + DH * DH + h;
        #pragma unroll 4
        for (int k = 0; k < DH; k++) {
            float wl = Wl[k * DH], wr = Wr[k * DH];
            u64 wl2 = f2_pack(wl, wl), wr2 = f2_pack(wr, wr);
            const u64* pr = reinterpret_cast<const u64*>(PT) + k * (PITCH / 2);
            #pragma unroll
            for (int j2 = 0; j2 < 16; j2++) {
                u64 vv = pr[j2];
                accA[j2] = f2_fma(vv, wl2, accA[j2]);
                accB[j2] = f2_fma(vv, wr2, accB[j2]);
            }
        }
        float bm = bm2[h];
        u64 bmp = f2_pack(bm, bm);
        #pragma unroll
        for (int j2 = 0; j2 < 16; j2++) accA[j2] = f2_add(accA[j2], bmp);
        __syncthreads();   // all warps done reading PT(v1) before agg2 overwrites it
        #pragma unroll 4
        for (int i2 = 0; i2 < 16; i2++) {
            float2 bB = f2_unpack(accB[i2]);
            u64 bx = f2_pack(bB.x, bB.x), by = f2_pack(bB.y, bB.y);
            u64 sx = 0, sy = 0;
            #pragma unroll
            for (int j2 = 0; j2 < 16; j2++) {
                u64 A = accA[j2];
                sx = f2_fma(f2_relu2x(f2_add(A, bx)), HALF2, sx);
                sy = f2_fma(f2_relu2x(f2_add(A, by)), HALF2, sy);
            }
            float2 fx = f2_unpack(sx), fy = f2_unpack(sy);
            float2 aA = f2_unpack(accA[i2]);
            float gx = fx.x + fx.y - fmaxf(aA.x + bB.x, 0.f);
            float gy = fy.x + fy.y - fmaxf(aA.y + bB.y, 0.f);
            *reinterpret_cast<u64*>(&PT[h * PITCH + 2 * i2]) = f2_pack(gx, gy);
        }
    }
    __syncthreads();

    // ================= Layer 2: update + max =================
    float m = -INFINITY;
    {
        #pragma unroll
        for (int i2 = 0; i2 < 16; i2++) vacc[i2] = 0;
        const float* Wu = g_Wt_up2 + h;
        #pragma unroll 4
        for (int k = 0; k < DSA; k++) {
            float w = Wu[k * DH];
            u64 w2 = f2_pack(w, w);
            const u64* xr = reinterpret_cast<const u64*>(xsT) + k * (PITCH / 2);
            #pragma unroll
            for (int i2 = 0; i2 < 16; i2++) vacc[i2] = f2_fma(xr[i2], w2, vacc[i2]);
        }
        #pragma unroll 4
        for (int k = 0; k < DH; k++) {
            float w = Wu[(DSA + k) * DH];
            u64 w2 = f2_pack(w, w);
            const u64* pr = reinterpret_cast<const u64*>(PT) + k * (PITCH / 2);
            #pragma unroll
            for (int i2 = 0; i2 < 16; i2++) vacc[i2] = f2_fma(pr[i2], w2, vacc[i2]);
        }
        float bu = bu2[h];
        u64 bup = f2_pack(bu, bu);
        #pragma unroll
        for (int i2 = 0; i2 < 16; i2++) {
            float2 f = f2_unpack(f2_add(vacc[i2], bup));
            m = fmaxf(m, fmaxf(f.x, f.y));
        }
        m = fmaxf(m, 0.f);   // relu then max == max then relu
    }

    // out[b] = sum_h m[h] * Wv[h] + bv
    float contrib = m * Wv[h];
    #pragma unroll
    for (int o = 16; o; o >>= 1)
        contrib += __shfl_xor_sync(0xffffffffu, contrib, o);
    if ((h & 31) == 0) red[h >> 5] = contrib;
    __syncthreads();
    if (h == 0) out[b] = red[0] + red[1] + red[2] + red[3] + bv[0];
}

extern "C" void kernel_launch(void* const* d_in, const int* in_sizes, int n_in,
                              void* d_out, int out_size) {
    const float* x   = (const float*)d_in[0];
    // d_in[1] = ext_adj (structure folded into the agg loop)
    const float* Wm1 = (const float*)d_in[2];
    const float* bm1 = (const float*)d_in[3];
    const float* Wm2 = (const float*)d_in[4];
    const float* bm2 = (const float*)d_in[5];
    const float* Wu1 = (const float*)d_in[6];
    const float* bu1 = (const float*)d_in[7];
    const float* Wu2 = (const float*)d_in[8];
    const float* bu2 = (const float*)d_in[9];
    const float* Wv  = (const float*)d_in[10];
    const float* bv  = (const float*)d_in[11];

    transpose_weights_kernel<<<72, 256>>>(Wm1, Wm2, Wu1, Wu2);
    msggraph_kernel<<<NB, 128>>>(x, bm1, bm2, bu1, bu2, Wv, bv, (float*)d_out);
}